// round 16
// baseline (speedup 1.0000x reference)
#include <cuda_runtime.h>
#include <math.h>

#define BQ 8
#define TQ 96
#define NQ 20000
#define PQ 12
#define LQ 3
#define DQ 32
#define CQ 128
#define MQ 64
#define NT64 313   /* ceil(20000/64) */

// ---------------- scratch (static device globals; no allocation) ----------------
__device__ float g_h   [BQ*NQ*CQ + 128*CQ];  // padded (zero-init .bss) for last tile
__device__ float g_h0  [BQ*NQ*CQ];
__device__ float g_phiq[BQ*NQ*MQ];
__device__ float g_phik[BQ*NQ*MQ];
__device__ float g_A1  [NQ*DQ];
__device__ float g_A2  [NQ*DQ];
__device__ float g_kv  [BQ*MQ*CQ];
__device__ float g_ksum[BQ*MQ];
__device__ unsigned int g_kmax[BQ];
__device__ float g_T1[BQ*DQ], g_T2[BQ*DQ], g_bias2[BQ*DQ];
__device__ float g_te[BQ*DQ], g_we[BQ*DQ];

union F2U { float2 f; unsigned long long u; };
__device__ __forceinline__ float2 ffma2(float2 a, float2 b, float2 c) {
    F2U A, Bv, Cv, Dv; A.f = a; Bv.f = b; Cv.f = c;
    asm("fma.rn.f32x2 %0, %1, %2, %3;" : "=l"(Dv.u) : "l"(A.u), "l"(Bv.u), "l"(Cv.u));
    return Dv.f;
}
__device__ __forceinline__ float2 fdup(float x) { return make_float2(x, x); }
__device__ __forceinline__ unsigned fkey(float f) {
    unsigned u = __float_as_uint(f);
    return (u & 0x80000000u) ? ~u : (u | 0x80000000u);
}
__device__ __forceinline__ float fdec(unsigned k) {
    unsigned u = (k & 0x80000000u) ? (k ^ 0x80000000u) : ~k;
    return __uint_as_float(u);
}

#define SCALE_RF 0.4204482076268573f   /* 32^(-1/4) */
#define RATIO_RF 0.125f                /* 1/sqrt(64) */
#define EPS_RF   1e-6f
#define IST      2.0f                  /* 1/sqrt(tau) */

// ---------------- K0: per-batch precompute (unchanged) ----------------
__global__ void k_prep(const float* __restrict__ x_mark, const float* __restrict__ time_tab,
                       const float* __restrict__ week_tab, const float* __restrict__ input_w,
                       const float* __restrict__ input_b,
                       const float* __restrict__ w1_w, const float* __restrict__ w1_b,
                       const float* __restrict__ w2_w, const float* __restrict__ w2_b) {
    int b = blockIdx.x, t = threadIdx.x;
    __shared__ float m0[TQ], m1[TQ];
    __shared__ int s_tod, s_dow;
    if (t < TQ) { m0[t] = x_mark[(b*TQ + t)*2 + 0]; m1[t] = x_mark[(b*TQ + t)*2 + 1]; }
    __syncthreads();
    if (t == 0) {
        int tod = (int)(m0[TQ-1] * (float)TQ); tod = min(max(tod, 0), TQ-1);
        int dow = (int)(m1[TQ-1] * 7.0f);      dow = min(max(dow, 0), 6);
        s_tod = tod; s_dow = dow;
    }
    __syncthreads();
    if (t < DQ) {
        int c = t;
        float a1 = w1_b[c], a2 = w2_b[c];
        #pragma unroll
        for (int g = 0; g < DQ; g++) {
            float te = time_tab[s_tod*DQ + g], we = week_tab[s_dow*DQ + g];
            a1 += te * w1_w[c*96 + 32 + g] + we * w1_w[c*96 + 64 + g];
            a2 += te * w2_w[c*96 + 32 + g] + we * w2_w[c*96 + 64 + g];
        }
        g_T1[b*DQ + c] = IST * a1;
        g_T2[b*DQ + c] = IST * a2;
        float bb = input_b[c];
        for (int tt = 0; tt < TQ; tt++)
            bb += m0[tt] * input_w[c*288 + 96 + tt] + m1[tt] * input_w[c*288 + 192 + tt];
        g_bias2[b*DQ + c] = bb;
        g_te[b*DQ + c] = time_tab[s_tod*DQ + c];
        g_we[b*DQ + c] = week_tab[s_dow*DQ + c];
    }
    if (t < MQ) g_ksum[b*MQ + t] = 0.0f;
    if (t == 0) g_kmax[b] = 0u;
}

// ---------------- K1 (unchanged) ----------------
__global__ void k_nodeA(const float* __restrict__ node_emb,
                        const float* __restrict__ w1_w, const float* __restrict__ w2_w) {
    __shared__ float w1s[32*33], w2s[32*33], ne[8*33];
    int t = threadIdx.x;
    for (int i = 0; i < 4; i++) {
        int idx = i*256 + t; int c = idx >> 5, g = idx & 31;
        w1s[c*33 + g] = w1_w[c*96 + g];
        w2s[c*33 + g] = w2_w[c*96 + g];
    }
    { int row = t >> 5, g = t & 31; ne[row*33 + g] = node_emb[(blockIdx.x*8 + row)*DQ + g]; }
    __syncthreads();
    int row = t >> 5, c = t & 31;
    int n = blockIdx.x*8 + row;
    float a1 = 0.f, a2 = 0.f;
    #pragma unroll
    for (int g = 0; g < 32; g++) {
        float nv = ne[row*33 + g];
        a1 += nv * w1s[c*33 + g];
        a2 += nv * w2s[c*33 + g];
    }
    g_A1[n*DQ + c] = IST * a1;
    g_A2[n*DQ + c] = IST * a2;
}

// ---------------- K2 (unchanged) ----------------
__global__ void k_embed(const float* __restrict__ x, const float* __restrict__ input_w,
                        const float* __restrict__ node_emb) {
    __shared__ float ws[TQ*36];
    int t = threadIdx.x, b = blockIdx.y;
    for (int i = 0; i < 12; i++) {
        int idx = i*256 + t;
        if (idx < TQ*DQ) { int c = idx / TQ, tt = idx % TQ; ws[tt*36 + c] = input_w[c*288 + tt]; }
    }
    __syncthreads();
    int n = blockIdx.x*256 + t;
    if (n >= NQ) return;
    float acc[32];
    #pragma unroll
    for (int c = 0; c < 32; c++) acc[c] = 0.f;
    for (int tt = 0; tt < TQ; tt++) {
        float xv = x[(b*TQ + tt)*NQ + n];
        const float4* wrow = (const float4*)&ws[tt*36];
        #pragma unroll
        for (int c4 = 0; c4 < 8; c4++) {
            float4 w = wrow[c4];
            acc[4*c4+0] += xv * w.x; acc[4*c4+1] += xv * w.y;
            acc[4*c4+2] += xv * w.z; acc[4*c4+3] += xv * w.w;
        }
    }
    int base = (b*NQ + n)*CQ;
    const float4* b4  = (const float4*)&g_bias2[b*DQ];
    const float4* te4 = (const float4*)&g_te[b*DQ];
    const float4* we4 = (const float4*)&g_we[b*DQ];
    const float4* ne4 = (const float4*)&node_emb[n*DQ];
    #pragma unroll
    for (int c4 = 0; c4 < 8; c4++) {
        float4 bb = b4[c4];
        float4 v = make_float4(acc[4*c4+0]+bb.x, acc[4*c4+1]+bb.y, acc[4*c4+2]+bb.z, acc[4*c4+3]+bb.w);
        ((float4*)&g_h [base])[c4] = v;  ((float4*)&g_h0[base])[c4] = v;
        float4 nv = ne4[c4];
        ((float4*)&g_h [base+32])[c4] = nv; ((float4*)&g_h0[base+32])[c4] = nv;
        float4 tv = te4[c4];
        ((float4*)&g_h [base+64])[c4] = tv; ((float4*)&g_h0[base+64])[c4] = tv;
        float4 wv = we4[c4];
        ((float4*)&g_h [base+96])[c4] = wv; ((float4*)&g_h0[base+96])[c4] = wv;
    }
}

// ---------------- K3 (unchanged) ----------------
__global__ void k_phi1(const float* __restrict__ proj) {
    __shared__ float proj_s[MQ*33];
    __shared__ float nv1_s[32*33], nv2_s[32*33];
    __shared__ float diag1[32], diag2[32];
    __shared__ unsigned s_bmax;
    int t = threadIdx.x, b = blockIdx.y;
    int n0 = blockIdx.x * 32;
    if (t == 0) s_bmax = 0u;
    for (int i = 0; i < 8; i++) {
        int idx = i*256 + t; int m = idx >> 5, d = idx & 31;
        proj_s[m*33 + d] = proj[m*32 + d];
    }
    for (int i = 0; i < 4; i++) {
        int idx = i*256 + t; int r = idx >> 5, d = idx & 31;
        nv1_s[r*33 + d] = g_A1[(n0 + r)*DQ + d] + g_T1[b*DQ + d];
        nv2_s[r*33 + d] = g_A2[(n0 + r)*DQ + d] + g_T2[b*DQ + d];
    }
    __syncthreads();
    if (t < 64) {
        int r = t & 31;
        const float* src = (t < 32) ? &nv1_s[r*33] : &nv2_s[r*33];
        float s = 0.f;
        #pragma unroll
        for (int d = 0; d < 32; d++) { float v = src[d]; s += v*v; }
        float dg = 0.5f * SCALE_RF * SCALE_RF * s;
        if (t < 32) diag1[r] = dg; else diag2[r] = dg;
    }
    __syncthreads();
    int r = t >> 3, j = t & 7;
    int base = (b*NQ + n0 + r)*MQ;
    {
        float nvr[32];
        #pragma unroll
        for (int d = 0; d < 32; d++) nvr[d] = nv1_s[r*33 + d];
        float dq[8];
        #pragma unroll
        for (int k = 0; k < 8; k++) {
            int m = j + 8*k; float s = 0.f;
            #pragma unroll
            for (int d = 0; d < 32; d++) s += nvr[d] * proj_s[m*33 + d];
            dq[k] = s * SCALE_RF;
        }
        float mx = dq[0];
        #pragma unroll
        for (int k = 1; k < 8; k++) mx = fmaxf(mx, dq[k]);
        #pragma unroll
        for (int off = 1; off < 8; off <<= 1)
            mx = fmaxf(mx, __shfl_xor_sync(0xffffffffu, mx, off));
        float dg = diag1[r];
        #pragma unroll
        for (int k = 0; k < 8; k++)
            g_phiq[base + j + 8*k] = RATIO_RF * (__expf(dq[k] - dg - mx) + EPS_RF);
    }
    {
        float nvr[32];
        #pragma unroll
        for (int d = 0; d < 32; d++) nvr[d] = nv2_s[r*33 + d];
        float mxk = -1e30f, dg = diag2[r];
        #pragma unroll
        for (int k = 0; k < 8; k++) {
            int m = j + 8*k; float s = 0.f;
            #pragma unroll
            for (int d = 0; d < 32; d++) s += nvr[d] * proj_s[m*33 + d];
            float dk = s * SCALE_RF;
            mxk = fmaxf(mxk, dk);
            g_phik[base + m] = dk - dg;
        }
        #pragma unroll
        for (int off = 1; off < 32; off <<= 1)
            mxk = fmaxf(mxk, __shfl_xor_sync(0xffffffffu, mxk, off));
        if ((t & 31) == 0) atomicMax(&s_bmax, fkey(mxk));
    }
    __syncthreads();
    if (t == 0) atomicMax(&g_kmax[b], s_bmax);
}

// ---------------- K4/K5/K6 (unchanged) ----------------
__global__ void k_phi2() {
    __shared__ float red[4][MQ];
    int t = threadIdx.x, b = blockIdx.y;
    int m = t & 63, g = t >> 6;
    float kmaxf = fdec(g_kmax[b]);
    int n0 = blockIdx.x * 500;
    float s = 0.f;
    for (int n = n0 + g; n < n0 + 500; n += 4) {
        int idx = (b*NQ + n)*MQ + m;
        float v = RATIO_RF * (__expf(g_phik[idx] - kmaxf) + EPS_RF);
        g_phik[idx] = v;
        s += v;
    }
    red[g][m] = s;
    __syncthreads();
    if (t < MQ) atomicAdd(&g_ksum[b*MQ + t], red[0][t] + red[1][t] + red[2][t] + red[3][t]);
}

__global__ void k_den() {
    __shared__ float ks[MQ];
    int t = threadIdx.x, b = blockIdx.y;
    if (t < MQ) ks[t] = g_ksum[b*MQ + t];
    __syncthreads();
    int w = t >> 5, l = t & 31;
    int n = blockIdx.x*8 + w;
    int base = (b*NQ + n)*MQ;
    float v0 = g_phiq[base + l], v1 = g_phiq[base + 32 + l];
    float p = v0 * ks[l] + v1 * ks[32 + l];
    #pragma unroll
    for (int off = 1; off < 32; off <<= 1)
        p += __shfl_xor_sync(0xffffffffu, p, off);
    float inv = 1.0f / p;
    g_phiq[base + l] = v0 * inv;
    g_phiq[base + 32 + l] = v1 * inv;
}

__global__ void k_zero() {
    int idx = (blockIdx.x*256 + threadIdx.x) * 8;
    #pragma unroll
    for (int i = 0; i < 8; i++) g_kv[idx + i] = 0.f;
}

// ---------------- K7 (REWRITTEN): lane=node gate GEMMs + lane=channel kv ----------------
// smem floats: wIn[128*132] @0, wOut @16896, hS[64*132] @33792, uS[64*132] @42240,
//              phS[64*64] @50688.  Total 54784 floats = 219136 B.
#define K7_SMEM (219136)
__global__ __launch_bounds__(256, 1)
void k_gatekv(int layer,
              const float* __restrict__ in_w,  const float* __restrict__ in_b,
              const float* __restrict__ out_w, const float* __restrict__ out_b) {
    extern __shared__ float sm[];
    float* wIn  = sm;
    float* wOut = sm + 16896;
    float* hS   = sm + 33792;   // [node][c] stride 132
    float* uS   = sm + 42240;   // [node][c] stride 132
    float* phS  = sm + 50688;   // [node][m] stride 64

    __shared__ float s_bin[CQ], s_bout[CQ];

    int t = threadIdx.x, b = blockIdx.y;
    int w = t >> 5, l = t & 31;

    // stage transposed weights [c][g] and biases
    for (int i = t; i < CQ*CQ; i += 256) {
        int c = i >> 7, g = i & 127;
        wIn [c*132 + g] = in_w [(layer*CQ + c)*CQ + g];
        wOut[c*132 + g] = out_w[(layer*CQ + c)*CQ + g];
    }
    if (t < CQ) { s_bin[t] = in_b[layer*CQ + t]; s_bout[t] = out_b[layer*CQ + t]; }

    int cbase = w * 16;                    // phase-1: warp owns 16 output channels
    int wc = w & 1, wm = w >> 1;           // phase-2 mapping
    int m0 = wm * 16, c0 = wc*64 + 2*l;

    float2 kvacc[16];
    #pragma unroll
    for (int i = 0; i < 16; i++) kvacc[i] = make_float2(0.f, 0.f);

    for (int tile = blockIdx.x; tile < NT64; tile += 18) {
        int n0 = tile * 64;
        int nv = min(64, NQ - n0);
        __syncthreads();
        // stage h tile [64][128] and phi_k [64][64]
        for (int i = 0; i < 32; i++) {
            int idx = i*256 + t; int n = idx >> 7, c = idx & 127;
            hS[n*132 + c] = g_h[(b*NQ + n0 + n)*CQ + c];
        }
        for (int i = 0; i < 16; i++) {
            int idx = i*256 + t; int n = idx >> 6, m = idx & 63;
            phS[idx] = (n < nv) ? g_phik[(b*NQ + n0 + n)*MQ + m] : 0.f;
        }
        __syncthreads();

        // ---- phase 1: gates. thread = (node l, node l+32) x 16 channels ----
        float2 aI[16], aO[16];
        #pragma unroll
        for (int j = 0; j < 16; j++) {
            aI[j] = fdup(s_bin [cbase + j]);
            aO[j] = fdup(s_bout[cbase + j]);
        }
        #pragma unroll 4
        for (int gb = 0; gb < 128; gb += 4) {
            float4 ha = *(const float4*)&hS[l*132 + gb];
            float4 hb = *(const float4*)&hS[(l+32)*132 + gb];
            float2 h0 = make_float2(ha.x, hb.x);
            float2 h1 = make_float2(ha.y, hb.y);
            float2 h2 = make_float2(ha.z, hb.z);
            float2 h3 = make_float2(ha.w, hb.w);
            #pragma unroll
            for (int j = 0; j < 16; j++) {
                float4 wi = *(const float4*)&wIn[(cbase + j)*132 + gb];
                aI[j] = ffma2(h0, fdup(wi.x), aI[j]);
                aI[j] = ffma2(h1, fdup(wi.y), aI[j]);
                aI[j] = ffma2(h2, fdup(wi.z), aI[j]);
                aI[j] = ffma2(h3, fdup(wi.w), aI[j]);
                float4 wo = *(const float4*)&wOut[(cbase + j)*132 + gb];
                aO[j] = ffma2(h0, fdup(wo.x), aO[j]);
                aO[j] = ffma2(h1, fdup(wo.y), aO[j]);
                aO[j] = ffma2(h2, fdup(wo.z), aO[j]);
                aO[j] = ffma2(h3, fdup(wo.w), aO[j]);
            }
        }
        // u = sigmoid(aI)*aO
        #pragma unroll
        for (int j = 0; j < 16; j++) {
            int c = cbase + j;
            uS[l*132 + c]      = aO[j].x / (1.f + __expf(-aI[j].x));
            uS[(l+32)*132 + c] = aO[j].y / (1.f + __expf(-aI[j].y));
        }
        __syncthreads();

        // ---- phase 2: kv += phi_k^T u. thread = (m0..m0+15) x (c0, c0+1) ----
        #pragma unroll 2
        for (int n = 0; n < 64; n++) {
            float2 u2 = *(const float2*)&uS[n*132 + c0];
            const float* pr = &phS[n*64 + m0];
            float4 p0 = *(const float4*)&pr[0];
            float4 p1 = *(const float4*)&pr[4];
            float4 p2 = *(const float4*)&pr[8];
            float4 p3 = *(const float4*)&pr[12];
            kvacc[0]  = ffma2(u2, fdup(p0.x), kvacc[0]);
            kvacc[1]  = ffma2(u2, fdup(p0.y), kvacc[1]);
            kvacc[2]  = ffma2(u2, fdup(p0.z), kvacc[2]);
            kvacc[3]  = ffma2(u2, fdup(p0.w), kvacc[3]);
            kvacc[4]  = ffma2(u2, fdup(p1.x), kvacc[4]);
            kvacc[5]  = ffma2(u2, fdup(p1.y), kvacc[5]);
            kvacc[6]  = ffma2(u2, fdup(p1.z), kvacc[6]);
            kvacc[7]  = ffma2(u2, fdup(p1.w), kvacc[7]);
            kvacc[8]  = ffma2(u2, fdup(p2.x), kvacc[8]);
            kvacc[9]  = ffma2(u2, fdup(p2.y), kvacc[9]);
            kvacc[10] = ffma2(u2, fdup(p2.z), kvacc[10]);
            kvacc[11] = ffma2(u2, fdup(p2.w), kvacc[11]);
            kvacc[12] = ffma2(u2, fdup(p3.x), kvacc[12]);
            kvacc[13] = ffma2(u2, fdup(p3.y), kvacc[13]);
            kvacc[14] = ffma2(u2, fdup(p3.z), kvacc[14]);
            kvacc[15] = ffma2(u2, fdup(p3.w), kvacc[15]);
        }
    }
    #pragma unroll
    for (int j = 0; j < 16; j++) {
        atomicAdd(&g_kv[(b*MQ + m0 + j)*CQ + c0    ], kvacc[j].x);
        atomicAdd(&g_kv[(b*MQ + m0 + j)*CQ + c0 + 1], kvacc[j].y);
    }
}

// ---------------- K8 (REWRITTEN): kv in registers, lane=channel-pair ----------------
#define K8_SMEM ((64*64 + 64*132) * 4)
__global__ __launch_bounds__(256, 1)
void k_apply(int layer, const float* __restrict__ ln_g, const float* __restrict__ ln_b) {
    extern __shared__ float sm[];
    float* phiS = sm;            // [node][m] stride 64
    float* hout = sm + 4096;     // [node][c] stride 132

    int t = threadIdx.x, b = blockIdx.y;
    int w = t >> 5, l = t & 31;
    int wc = w & 1, nb = (w >> 1) * 16;
    int c0 = wc*64 + 2*l;

    float2 kvreg[64];
    #pragma unroll
    for (int m = 0; m < 64; m++)
        kvreg[m] = *(const float2*)&g_kv[(b*MQ + m)*CQ + c0];

    float4 lg4 = *(const float4*)&ln_g[layer*CQ + 4*l];
    float4 lb4 = *(const float4*)&ln_b[layer*CQ + 4*l];

    for (int tile = blockIdx.x; tile < NT64; tile += 18) {
        int n0 = tile * 64;
        int nv = min(64, NQ - n0);
        __syncthreads();
        for (int i = 0; i < 16; i++) {
            int idx = i*256 + t; int n = idx >> 6, m = idx & 63;
            phiS[idx] = (n < nv) ? g_phiq[(b*NQ + n0 + n)*MQ + m] : 0.f;
        }
        __syncthreads();

        #pragma unroll 2
        for (int k = 0; k < 16; k++) {
            int n = nb + k;
            const float* pr = &phiS[n*64];
            float2 a0 = make_float2(0.f,0.f), a1 = a0, a2 = a0, a3 = a0;
            #pragma unroll
            for (int q = 0; q < 4; q++) {
                float4 pA = *(const float4*)&pr[q*16 + 0];
                float4 pB = *(const float4*)&pr[q*16 + 4];
                float4 pC = *(const float4*)&pr[q*16 + 8];
                float4 pD = *(const float4*)&pr[q*16 + 12];
                a0 = ffma2(kvreg[q*16+0],  fdup(pA.x), a0);
                a1 = ffma2(kvreg[q*16+1],  fdup(pA.y), a1);
                a2 = ffma2(kvreg[q*16+2],  fdup(pA.z), a2);
                a3 = ffma2(kvreg[q*16+3],  fdup(pA.w), a3);
                a0 = ffma2(kvreg[q*16+4],  fdup(pB.x), a0);
                a1 = ffma2(kvreg[q*16+5],  fdup(pB.y), a1);
                a2 = ffma2(kvreg[q*16+6],  fdup(pB.z), a2);
                a3 = ffma2(kvreg[q*16+7],  fdup(pB.w), a3);
                a0 = ffma2(kvreg[q*16+8],  fdup(pC.x), a0);
                a1 = ffma2(kvreg[q*16+9],  fdup(pC.y), a1);
                a2 = ffma2(kvreg[q*16+10], fdup(pC.z), a2);
                a3 = ffma2(kvreg[q*16+11], fdup(pC.w), a3);
                a0 = ffma2(kvreg[q*16+12], fdup(pD.x), a0);
                a1 = ffma2(kvreg[q*16+13], fdup(pD.y), a1);
                a2 = ffma2(kvreg[q*16+14], fdup(pD.z), a2);
                a3 = ffma2(kvreg[q*16+15], fdup(pD.w), a3);
            }
            float2 r = *(const float2*)&g_h[(b*NQ + n0 + n)*CQ + c0];
            float sx = a0.x + a1.x + a2.x + a3.x + r.x;
            float sy = a0.y + a1.y + a2.y + a3.y + r.y;
            hout[n*132 + c0]     = sx;
            hout[n*132 + c0 + 1] = sy;
        }
        __syncthreads();

        // LayerNorm: warp per node, 8 reps cover 64 nodes
        for (int rep = 0; rep < 8; rep++) {
            int node = rep*8 + w;
            float4 v = *(const float4*)&hout[node*132 + 4*l];
            float s  = v.x + v.y + v.z + v.w;
            float s2 = v.x*v.x + v.y*v.y + v.z*v.z + v.w*v.w;
            #pragma unroll
            for (int off = 1; off < 32; off <<= 1) {
                s  += __shfl_xor_sync(0xffffffffu, s,  off);
                s2 += __shfl_xor_sync(0xffffffffu, s2, off);
            }
            float mu  = s * (1.0f/128.0f);
            float var = s2 * (1.0f/128.0f) - mu*mu;
            float rstd = rsqrtf(var + 1e-5f);
            float4 o;
            o.x = (v.x - mu)*rstd*lg4.x + lb4.x;
            o.y = (v.y - mu)*rstd*lg4.y + lb4.y;
            o.z = (v.z - mu)*rstd*lg4.z + lb4.z;
            o.w = (v.w - mu)*rstd*lg4.w + lb4.w;
            if (n0 + node < NQ)
                *(float4*)&g_h[(b*NQ + n0 + node)*CQ + 4*l] = o;
        }
    }
}

// ---------------- K9 (unchanged) ----------------
__global__ void k_reg(const float* __restrict__ reg_w, const float* __restrict__ reg_b,
                      float* __restrict__ out) {
    __shared__ float rw[PQ*256];
    __shared__ float rb[PQ];
    int t = threadIdx.x, b = blockIdx.y;
    for (int i = 0; i < 12; i++) rw[i*256 + t] = reg_w[i*256 + t];
    if (t < PQ) rb[t] = reg_b[t];
    __syncthreads();
    int w = t >> 5, l = t & 31;
    int n = blockIdx.x*8 + w;
    int base = (b*NQ + n)*CQ;
    float4 s4 = *(const float4*)&g_h0[base + 4*l];
    float4 h4 = *(const float4*)&g_h [base + 4*l];
    float acc[PQ];
    #pragma unroll
    for (int p = 0; p < PQ; p++) {
        float4 a = *(const float4*)&rw[p*256 + 4*l];
        float4 c2 = *(const float4*)&rw[p*256 + 128 + 4*l];
        acc[p] = s4.x*a.x + s4.y*a.y + s4.z*a.z + s4.w*a.w
               + h4.x*c2.x + h4.y*c2.y + h4.z*c2.z + h4.w*c2.w;
    }
    #pragma unroll
    for (int p = 0; p < PQ; p++) {
        #pragma unroll
        for (int off = 1; off < 32; off <<= 1)
            acc[p] += __shfl_xor_sync(0xffffffffu, acc[p], off);
    }
    if (l == 0) {
        #pragma unroll
        for (int p = 0; p < PQ; p++)
            out[(b*PQ + p)*NQ + n] = acc[p] + rb[p];
    }
}

// ---------------- driver ----------------
extern "C" void kernel_launch(void* const* d_in, const int* in_sizes, int n_in,
                              void* d_out, int out_size) {
    const float* x        = (const float*)d_in[0];
    const float* x_mark   = (const float*)d_in[1];
    const float* node_emb = (const float*)d_in[2];
    const float* time_tab = (const float*)d_in[3];
    const float* week_tab = (const float*)d_in[4];
    const float* input_w  = (const float*)d_in[5];
    const float* input_b  = (const float*)d_in[6];
    const float* w1_w     = (const float*)d_in[7];
    const float* w1_b     = (const float*)d_in[8];
    const float* w2_w     = (const float*)d_in[9];
    const float* w2_b     = (const float*)d_in[10];
    const float* in_w     = (const float*)d_in[11];
    const float* in_b     = (const float*)d_in[12];
    const float* out_w    = (const float*)d_in[13];
    const float* out_b    = (const float*)d_in[14];
    const float* ln_g     = (const float*)d_in[15];
    const float* ln_b     = (const float*)d_in[16];
    const float* reg_w    = (const float*)d_in[17];
    const float* reg_b    = (const float*)d_in[18];
    const float* proj     = (const float*)d_in[19];
    float* out = (float*)d_out;

    static int attr_done = 0;
    if (!attr_done) {
        cudaFuncSetAttribute(k_gatekv, cudaFuncAttributeMaxDynamicSharedMemorySize, K7_SMEM);
        cudaFuncSetAttribute(k_apply,  cudaFuncAttributeMaxDynamicSharedMemorySize, K8_SMEM);
        attr_done = 1;
    }

    k_prep<<<BQ, 128>>>(x_mark, time_tab, week_tab, input_w, input_b, w1_w, w1_b, w2_w, w2_b);
    k_nodeA<<<NQ/8, 256>>>(node_emb, w1_w, w2_w);
    k_embed<<<dim3((NQ + 255)/256, BQ), 256>>>(x, input_w, node_emb);
    k_phi1<<<dim3(NQ/32, BQ), 256>>>(proj);
    k_phi2<<<dim3(40, BQ), 256>>>();
    k_den<<<dim3(NQ/8, BQ), 256>>>();

    for (int layer = 0; layer < LQ; layer++) {
        k_zero<<<32, 256>>>();
        k_gatekv<<<dim3(18, BQ), 256, K7_SMEM>>>(layer, in_w, in_b, out_w, out_b);
        k_apply<<<dim3(18, BQ), 256, K8_SMEM>>>(layer, ln_g, ln_b);
    }
    k_reg<<<dim3(NQ/8, BQ), 256>>>(reg_w, reg_b, out);
}